// round 4
// baseline (speedup 1.0000x reference)
#include <cuda_runtime.h>
#include <cuda_bf16.h>
#include <cstdint>
#include <math.h>

#define BATCH 4
#define SEQ   2048
#define DMODEL 1024
#define NH    8
#define HD    128
#define HDIM  1024

// ---------------------------------------------------------------------------
// Scratch (device globals: allocation-free rule)
// ---------------------------------------------------------------------------
__device__ float g_qkv[(size_t)BATCH * SEQ * 3 * HDIM];          // [B,T,3*HDIM]
__device__ float g_v[(size_t)BATCH * NH * SEQ * HD];             // [B,H,T,D] fp32
__device__ __nv_bfloat16 g_qh[(size_t)BATCH * NH * SEQ * HD];    // [B,H,T,D]
__device__ __nv_bfloat16 g_ql[(size_t)BATCH * NH * SEQ * HD];
__device__ __nv_bfloat16 g_kh[(size_t)BATCH * NH * SEQ * HD];
__device__ __nv_bfloat16 g_kl[(size_t)BATCH * NH * SEQ * HD];
__device__ __nv_bfloat16 g_vh[(size_t)BATCH * NH * HD * SEQ];    // [B,H,D,T]
__device__ __nv_bfloat16 g_vl[(size_t)BATCH * NH * HD * SEQ];
// pre-split GEMM operands
__device__ __nv_bfloat16 g_xh[(size_t)BATCH * SEQ * DMODEL];
__device__ __nv_bfloat16 g_xl[(size_t)BATCH * SEQ * DMODEL];
__device__ __nv_bfloat16 g_wqh[(size_t)3 * HDIM * DMODEL];
__device__ __nv_bfloat16 g_wql[(size_t)3 * HDIM * DMODEL];
__device__ __nv_bfloat16 g_wph[(size_t)DMODEL * HDIM];
__device__ __nv_bfloat16 g_wpl[(size_t)DMODEL * HDIM];
__device__ __nv_bfloat16 g_yh[(size_t)BATCH * SEQ * HDIM];       // flash out (split)
__device__ __nv_bfloat16 g_yl[(size_t)BATCH * SEQ * HDIM];

// ---------------------------------------------------------------------------
// PTX helpers (sm_80-class; valid at compute_103 target)
// ---------------------------------------------------------------------------
__device__ __forceinline__ uint32_t smem_u32(const void* p) {
    uint32_t a;
    asm("{ .reg .u64 t; cvta.to.shared.u64 t, %1; cvt.u32.u64 %0, t; }"
        : "=r"(a) : "l"(p));
    return a;
}

#define LDMX4(r, addr) \
    asm volatile("ldmatrix.sync.aligned.m8n8.x4.shared.b16 {%0,%1,%2,%3}, [%4];" \
        : "=r"((r)[0]), "=r"((r)[1]), "=r"((r)[2]), "=r"((r)[3]) : "r"(addr))

#define MMA_BF16(d, a, b0, b1) \
    asm volatile("mma.sync.aligned.m16n8k16.row.col.f32.bf16.bf16.f32 " \
        "{%0,%1,%2,%3},{%4,%5,%6,%7},{%8,%9},{%0,%1,%2,%3};" \
        : "+f"((d)[0]), "+f"((d)[1]), "+f"((d)[2]), "+f"((d)[3]) \
        : "r"((a)[0]), "r"((a)[1]), "r"((a)[2]), "r"((a)[3]), "r"(b0), "r"(b1))

#define CP_ASYNC16(dst, src) \
    asm volatile("cp.async.cg.shared.global [%0], [%1], 16;" :: "r"(dst), "l"(src) : "memory")
#define CP_COMMIT() asm volatile("cp.async.commit_group;" ::: "memory")
#define CP_WAIT0()  asm volatile("cp.async.wait_group 0;" ::: "memory")
#define CP_WAIT1()  asm volatile("cp.async.wait_group 1;" ::: "memory")

// pack two fp32 -> bf16x2 (e0 low half, e1 high half)
__device__ __forceinline__ uint32_t packbf(float e0, float e1) {
    uint32_t d;
    asm("cvt.rn.bf16x2.f32 %0, %1, %2;" : "=r"(d) : "f"(e1), "f"(e0));
    return d;
}
__device__ __forceinline__ float bfx2_lo(uint32_t p) { return __uint_as_float(p << 16); }
__device__ __forceinline__ float bfx2_hi(uint32_t p) { return __uint_as_float(p & 0xFFFF0000u); }

// ---------------------------------------------------------------------------
// split: fp32 -> bf16 hi/lo, vectorized 4 elems/thread
// ---------------------------------------------------------------------------
__global__ __launch_bounds__(256) void split_kernel(
    const float* __restrict__ src, __nv_bfloat16* __restrict__ hi,
    __nv_bfloat16* __restrict__ lo, int n4)
{
    int i = blockIdx.x * 256 + threadIdx.x;
    if (i < n4) {
        float4 v = ((const float4*)src)[i];
        uint32_t h0 = packbf(v.x, v.y), h1 = packbf(v.z, v.w);
        uint32_t l0 = packbf(v.x - bfx2_lo(h0), v.y - bfx2_hi(h0));
        uint32_t l1 = packbf(v.z - bfx2_lo(h1), v.w - bfx2_hi(h1));
        ((uint2*)hi)[i] = make_uint2(h0, h1);
        ((uint2*)lo)[i] = make_uint2(l0, l1);
    }
}

// ===========================================================================
// bf16-split GEMM: C[M,N](fp32) = (Ah+Al)[M,K] @ (Bh+Bl)[N,K]^T, 3-term mma.
// CTA 128x128, 8 warps (2x4, warp tile 64x32), K-chunk 32, 3-stage cp.async.
// smem stage: Ah|Al|Bh|Bl, each 128 rows x 80 B (odd 16B multiple -> ldmatrix
// conflict-free). 3 stages x 40960 = 122880 B.
// ===========================================================================
#define G_PART   10240
#define G_STAGE  40960
#define G_SMEM   (3 * G_STAGE)

__global__ __launch_bounds__(256, 1) void gemm_bf16s(
    const __nv_bfloat16* __restrict__ Ah, const __nv_bfloat16* __restrict__ Al,
    const __nv_bfloat16* __restrict__ Bh, const __nv_bfloat16* __restrict__ Bl,
    float* __restrict__ C, int Kd, int Nd)
{
    extern __shared__ char smem[];
    const uint32_t sb = smem_u32(smem);
    const int tid = threadIdx.x;
    const int wid = tid >> 5, lane = tid & 31;
    const int wm = wid >> 2, wn = wid & 3;
    const int m0 = blockIdx.y * 128, n0 = blockIdx.x * 128;
    const int nch = Kd / 32;

    const int prow = tid >> 2;          // 0..63  (x2 rows per thread? no: 512 chunks)
    // 512 16B-chunks per part: row = chunk>>2, col = chunk&3
    auto load_stage = [&](int c) {
        const uint32_t st = sb + (c % 3) * G_STAGE;
        const __nv_bfloat16* p0 = Ah + (size_t)m0 * Kd + c * 32;
        const __nv_bfloat16* p1 = Al + (size_t)m0 * Kd + c * 32;
        const __nv_bfloat16* p2 = Bh + (size_t)n0 * Kd + c * 32;
        const __nv_bfloat16* p3 = Bl + (size_t)n0 * Kd + c * 32;
#pragma unroll
        for (int i = 0; i < 2; i++) {
            const int cc = i * 256 + tid;          // 0..511
            const int row = cc >> 2, col = cc & 3;
            const uint32_t off = row * 80 + col * 16;
            const size_t gi = (size_t)row * Kd + col * 8;
            CP_ASYNC16(st + off,              p0 + gi);
            CP_ASYNC16(st + G_PART + off,     p1 + gi);
            CP_ASYNC16(st + 2 * G_PART + off, p2 + gi);
            CP_ASYNC16(st + 3 * G_PART + off, p3 + gi);
        }
    };

    float acc[4][4][4];
#pragma unroll
    for (int i = 0; i < 4; i++)
#pragma unroll
        for (int j = 0; j < 4; j++)
#pragma unroll
            for (int e = 0; e < 4; e++) acc[i][j][e] = 0.f;

    auto compute = [&](int s) {
        const uint32_t st = sb + s * G_STAGE;
        const uint32_t lrow = (lane & 15);
        const uint32_t lcol = (lane >> 4) * 16;
#pragma unroll
        for (int k16 = 0; k16 < 2; k16++) {
            const uint32_t kb2 = k16 * 32;
            uint32_t ah[4][4], al[4][4];
#pragma unroll
            for (int i = 0; i < 4; i++) {
                uint32_t aaddr = st + (wm * 64 + i * 16 + lrow) * 80 + kb2 + lcol;
                LDMX4(ah[i], aaddr);
                LDMX4(al[i], aaddr + G_PART);
            }
            uint32_t bh_[4][2], bl_[4][2];
#pragma unroll
            for (int jj = 0; jj < 2; jj++) {
                uint32_t r[4];
                uint32_t baddr = st + 2 * G_PART + (wn * 32 + jj * 16 + lrow) * 80 + kb2 + lcol;
                LDMX4(r, baddr);
                bh_[2 * jj][0] = r[0]; bh_[2 * jj][1] = r[2];
                bh_[2 * jj + 1][0] = r[1]; bh_[2 * jj + 1][1] = r[3];
                LDMX4(r, baddr + G_PART);
                bl_[2 * jj][0] = r[0]; bl_[2 * jj][1] = r[2];
                bl_[2 * jj + 1][0] = r[1]; bl_[2 * jj + 1][1] = r[3];
            }
#pragma unroll
            for (int i = 0; i < 4; i++)
#pragma unroll
                for (int j = 0; j < 4; j++) {
                    MMA_BF16(acc[i][j], ah[i], bh_[j][0], bh_[j][1]);
                    MMA_BF16(acc[i][j], al[i], bh_[j][0], bh_[j][1]);
                    MMA_BF16(acc[i][j], ah[i], bl_[j][0], bl_[j][1]);
                }
        }
    };

    // ---- 3-stage pipeline, 2 in flight, one sync per chunk ----
    load_stage(0); CP_COMMIT();
    if (nch > 1) { load_stage(1); CP_COMMIT(); }
    for (int c = 0; c < nch; c++) {
        if (c + 1 < nch) CP_WAIT1(); else CP_WAIT0();
        __syncthreads();
        if (c + 2 < nch) { load_stage(c + 2); CP_COMMIT(); }
        compute(c % 3);
    }

    // ---- epilogue ----
    const int r = lane >> 2;
    const int cb = (lane & 3) * 2;
#pragma unroll
    for (int i = 0; i < 4; i++) {
        const int row0 = m0 + wm * 64 + i * 16 + r;
#pragma unroll
        for (int j = 0; j < 4; j++) {
            const int col = n0 + wn * 32 + j * 8 + cb;
            *(float2*)(C + (size_t)row0 * Nd + col) = make_float2(acc[i][j][0], acc[i][j][1]);
            *(float2*)(C + (size_t)(row0 + 8) * Nd + col) = make_float2(acc[i][j][2], acc[i][j][3]);
        }
    }
}

// ---------------------------------------------------------------------------
// prep: per (b,t,h) RMS-norm q,k; RoPE; v-mix. Emits bf16-split Q,K [B,H,T,D]
// and fp32 V [B,H,T,D].
// ---------------------------------------------------------------------------
__global__ __launch_bounds__(128) void prep_kernel(
    const float* __restrict__ qkv, const float* __restrict__ ve,
    const float* __restrict__ lam,
    __nv_bfloat16* __restrict__ Qh, __nv_bfloat16* __restrict__ Ql,
    __nv_bfloat16* __restrict__ Kh, __nv_bfloat16* __restrict__ Kl,
    float* __restrict__ V)
{
    const int idx = blockIdx.x;
    const int h = idx % NH;
    const int bt = idx / NH;
    const int t = bt % SEQ;
    const int b = bt / SEQ;
    const int d = threadIdx.x;

    const float* base = qkv + (size_t)bt * 3 * HDIM;
    float qv = base[h * HD + d];
    float kv = base[HDIM + h * HD + d];
    float vv = base[2 * HDIM + h * HD + d];

    float sq = qv * qv, sk = kv * kv;
#pragma unroll
    for (int o = 16; o; o >>= 1) {
        sq += __shfl_xor_sync(0xffffffffu, sq, o);
        sk += __shfl_xor_sync(0xffffffffu, sk, o);
    }
    __shared__ float wq[4], wk[4];
    if ((d & 31) == 0) { wq[d >> 5] = sq; wk[d >> 5] = sk; }
    __syncthreads();
    float tq = (wq[0] + wq[1]) + (wq[2] + wq[3]);
    float tk = (wk[0] + wk[1]) + (wk[2] + wk[3]);
    const float EPS = 1.1920929e-7f;
    float rq = rsqrtf(tq * (1.0f / 128.0f) + EPS);
    float rk = rsqrtf(tk * (1.0f / 128.0f) + EPS);

    __shared__ float nq[128], nk[128];
    nq[d] = qv * rq;
    nk[d] = kv * rk;
    __syncthreads();

    const int i = d & 63;
    float c, s;
    if (i < 32) {
        float xi = (float)i / 31.0f;
        float f = (float)exp2(-10.0 * (double)xi);
        float th = (float)t * f;
        c = cosf(th);
        s = sinf(th);
    } else {
        c = 1.0f; s = 0.0f;
    }
    float qo, ko;
    if (d < 64) { qo = nq[d] * c + nq[d + 64] * s; ko = nk[d] * c + nk[d + 64] * s; }
    else        { qo = nq[d] * c - nq[d - 64] * s; ko = nk[d] * c - nk[d - 64] * s; }

    float vo = lam[0] * vv + lam[1] * ve[(size_t)bt * HDIM + h * HD + d];

    size_t o = ((size_t)(b * NH + h) * SEQ + t) * HD + d;
    __nv_bfloat16 qhi = __float2bfloat16(qo);
    __nv_bfloat16 khi = __float2bfloat16(ko);
    Qh[o] = qhi; Ql[o] = __float2bfloat16(qo - __bfloat162float(qhi));
    Kh[o] = khi; Kl[o] = __float2bfloat16(ko - __bfloat162float(khi));
    V[o] = vo;
}

// ---------------------------------------------------------------------------
// vtrans: V [BH][T][D] fp32 -> Vh/Vl [BH][D][T] bf16 split
// ---------------------------------------------------------------------------
__global__ __launch_bounds__(256) void vtrans_kernel(
    const float* __restrict__ V,
    __nv_bfloat16* __restrict__ Vh, __nv_bfloat16* __restrict__ Vl)
{
    __shared__ float tile[32][33];
    const int bh = blockIdx.z;
    const int t0 = blockIdx.x * 32, d0 = blockIdx.y * 32;
    const int tx = threadIdx.x & 31, ty = threadIdx.x >> 5;
    const float* src = V + (size_t)bh * SEQ * HD;
#pragma unroll
    for (int i = 0; i < 4; i++)
        tile[ty + i * 8][tx] = src[(size_t)(t0 + ty + i * 8) * HD + d0 + tx];
    __syncthreads();
    __nv_bfloat16* dh = Vh + (size_t)bh * HD * SEQ;
    __nv_bfloat16* dl = Vl + (size_t)bh * HD * SEQ;
#pragma unroll
    for (int i = 0; i < 4; i++) {
        float v = tile[tx][ty + i * 8];
        __nv_bfloat16 hi = __float2bfloat16(v);
        size_t o = (size_t)(d0 + ty + i * 8) * SEQ + t0 + tx;
        dh[o] = hi;
        dl[o] = __float2bfloat16(v - __bfloat162float(hi));
    }
}

// ===========================================================================
// Flash attention, bf16-split mma. 128 q-rows/CTA, 8 warps x 16 rows.
// Epilogue now emits pre-split bf16 Yh/Yl for the c_proj GEMM.
// ===========================================================================
#define FQ_PART 34816
#define FK_PART 17408
#define FV_PART 18432
#define FSTAGE  (2 * FK_PART + 2 * FV_PART)
#define FSTAGE0 (2 * FQ_PART)
#define F_SMEM  (FSTAGE0 + 2 * FSTAGE)

__global__ __launch_bounds__(256, 1) void flash_mma(
    const __nv_bfloat16* __restrict__ Qh, const __nv_bfloat16* __restrict__ Ql,
    const __nv_bfloat16* __restrict__ Kh, const __nv_bfloat16* __restrict__ Kl,
    const __nv_bfloat16* __restrict__ Vh, const __nv_bfloat16* __restrict__ Vl,
    __nv_bfloat16* __restrict__ Yh, __nv_bfloat16* __restrict__ Yl)
{
    extern __shared__ char smem[];
    const uint32_t sbase = smem_u32(smem);
    const int tid = threadIdx.x;
    const int wid = tid >> 5, lane = tid & 31;
    const int qt = gridDim.x - 1 - blockIdx.x;
    const int bh = blockIdx.y;
    const int b = bh >> 3, h = bh & 7;

    const size_t TD = (size_t)SEQ * HD;
    const __nv_bfloat16* qh_b = Qh + bh * TD;
    const __nv_bfloat16* ql_b = Ql + bh * TD;
    const __nv_bfloat16* kh_b = Kh + bh * TD;
    const __nv_bfloat16* kl_b = Kl + bh * TD;
    const __nv_bfloat16* vh_b = Vh + bh * TD;
    const __nv_bfloat16* vl_b = Vl + bh * TD;

#pragma unroll
    for (int i = 0; i < 16; i++) {
        int c = i * 256 + tid;
        int part = c >> 11;
        int c2 = c & 2047;
        int row = c2 >> 4, col = c2 & 15;
        uint32_t dst = sbase + part * FQ_PART + row * 272 + col * 16;
        const __nv_bfloat16* src = (part ? ql_b : qh_b) + (size_t)(qt * 128 + row) * 128 + col * 8;
        CP_ASYNC16(dst, src);
    }
    auto load_kv = [&](int kt, int s) {
        uint32_t kb = sbase + FSTAGE0 + s * FSTAGE;
#pragma unroll
        for (int i = 0; i < 4; i++) {
            int c = i * 256 + tid;
            int row = c >> 4, col = c & 15;
            uint32_t off = row * 272 + col * 16;
            size_t gi = (size_t)(kt * 64 + row) * 128 + col * 8;
            CP_ASYNC16(kb + off, kh_b + gi);
            CP_ASYNC16(kb + FK_PART + off, kl_b + gi);
        }
#pragma unroll
        for (int i = 0; i < 4; i++) {
            int c = i * 256 + tid;
            int row = c >> 3, col = c & 7;
            uint32_t off = row * 144 + col * 16;
            size_t gi = (size_t)row * SEQ + kt * 64 + col * 8;
            CP_ASYNC16(kb + 2 * FK_PART + off, vh_b + gi);
            CP_ASYNC16(kb + 2 * FK_PART + FV_PART + off, vl_b + gi);
        }
    };
    load_kv(0, 0);
    CP_COMMIT();

    float acc[16][4];
#pragma unroll
    for (int i = 0; i < 16; i++)
#pragma unroll
        for (int e = 0; e < 4; e++) acc[i][e] = 0.f;
    float m_i[2] = {-1e30f, -1e30f};
    float l_i[2] = {0.f, 0.f};

    const uint32_t lrow = lane & 15;
    const uint32_t lcol = (lane >> 4) * 16;
    const int nkt = 2 * qt + 2;
    const float SC = 0.08838834764831845f;

    for (int kt = 0; kt < nkt; kt++) {
        if (kt + 1 < nkt) {
            load_kv(kt + 1, (kt + 1) & 1);
            CP_COMMIT();
            CP_WAIT1();
        } else {
            CP_WAIT0();
        }
        __syncthreads();
        const uint32_t kb = sbase + FSTAGE0 + (kt & 1) * FSTAGE;

        float s[8][4];
#pragma unroll
        for (int j = 0; j < 8; j++)
#pragma unroll
            for (int e = 0; e < 4; e++) s[j][e] = 0.f;

        const uint32_t qrow = sbase + (wid * 16 + lrow) * 272 + lcol;
#pragma unroll
        for (int k16 = 0; k16 < 8; k16++) {
            uint32_t qa = qrow + k16 * 32;
            uint32_t ah[4], al[4];
            LDMX4(ah, qa);
            LDMX4(al, qa + FQ_PART);
#pragma unroll
            for (int jj = 0; jj < 4; jj++) {
                uint32_t ka = kb + (jj * 16 + lrow) * 272 + lcol + k16 * 32;
                uint32_t r[4];
                LDMX4(r, ka);
                MMA_BF16(s[2 * jj], ah, r[0], r[2]);
                MMA_BF16(s[2 * jj + 1], ah, r[1], r[3]);
                MMA_BF16(s[2 * jj], al, r[0], r[2]);
                MMA_BF16(s[2 * jj + 1], al, r[1], r[3]);
                LDMX4(r, ka + FK_PART);
                MMA_BF16(s[2 * jj], ah, r[0], r[2]);
                MMA_BF16(s[2 * jj + 1], ah, r[1], r[3]);
            }
        }

        const bool need_mask = (kt >= 2 * qt);
#pragma unroll
        for (int hh = 0; hh < 2; hh++) {
            const int rowg = qt * 128 + wid * 16 + (lane >> 2) + hh * 8;
            float mt = -1e30f;
#pragma unroll
            for (int j = 0; j < 8; j++) {
#pragma unroll
                for (int e = 0; e < 2; e++) {
                    float v = s[j][2 * hh + e] * SC;
                    if (need_mask) {
                        int colg = kt * 64 + j * 8 + (lane & 3) * 2 + e;
                        if (colg > rowg) v = -1e30f;
                    }
                    s[j][2 * hh + e] = v;
                    mt = fmaxf(mt, v);
                }
            }
            mt = fmaxf(mt, __shfl_xor_sync(0xffffffffu, mt, 1));
            mt = fmaxf(mt, __shfl_xor_sync(0xffffffffu, mt, 2));
            float mn = fmaxf(m_i[hh], mt);
            float corr = __expf(m_i[hh] - mn);
            m_i[hh] = mn;
            float rs = 0.f;
#pragma unroll
            for (int j = 0; j < 8; j++) {
#pragma unroll
                for (int e = 0; e < 2; e++) {
                    float p = __expf(s[j][2 * hh + e] - mn);
                    s[j][2 * hh + e] = p;
                    rs += p;
                }
            }
            rs += __shfl_xor_sync(0xffffffffu, rs, 1);
            rs += __shfl_xor_sync(0xffffffffu, rs, 2);
            l_i[hh] = l_i[hh] * corr + rs;
#pragma unroll
            for (int ot = 0; ot < 16; ot++) {
                acc[ot][2 * hh] *= corr;
                acc[ot][2 * hh + 1] *= corr;
            }
        }

        const uint32_t vb = kb + 2 * FK_PART;
#pragma unroll
        for (int kk = 0; kk < 4; kk++) {
            const int j0 = 2 * kk, j1 = 2 * kk + 1;
            uint32_t ahp[4], alp[4];
            ahp[0] = packbf(s[j0][0], s[j0][1]);
            ahp[1] = packbf(s[j0][2], s[j0][3]);
            ahp[2] = packbf(s[j1][0], s[j1][1]);
            ahp[3] = packbf(s[j1][2], s[j1][3]);
            alp[0] = packbf(s[j0][0] - bfx2_lo(ahp[0]), s[j0][1] - bfx2_hi(ahp[0]));
            alp[1] = packbf(s[j0][2] - bfx2_lo(ahp[1]), s[j0][3] - bfx2_hi(ahp[1]));
            alp[2] = packbf(s[j1][0] - bfx2_lo(ahp[2]), s[j1][1] - bfx2_hi(ahp[2]));
            alp[3] = packbf(s[j1][2] - bfx2_lo(ahp[3]), s[j1][3] - bfx2_hi(ahp[3]));
#pragma unroll
            for (int jj = 0; jj < 8; jj++) {
                uint32_t va = vb + (jj * 16 + lrow) * 144 + kk * 32 + lcol;
                uint32_t r[4];
                LDMX4(r, va);
                MMA_BF16(acc[2 * jj], ahp, r[0], r[2]);
                MMA_BF16(acc[2 * jj + 1], ahp, r[1], r[3]);
                MMA_BF16(acc[2 * jj], alp, r[0], r[2]);
                MMA_BF16(acc[2 * jj + 1], alp, r[1], r[3]);
                LDMX4(r, va + FV_PART);
                MMA_BF16(acc[2 * jj], ahp, r[0], r[2]);
                MMA_BF16(acc[2 * jj + 1], ahp, r[1], r[3]);
            }
        }
        __syncthreads();
    }

    // ---------- epilogue: write pre-split bf16 Y ----------
    const float inv0 = 1.f / l_i[0];
    const float inv1 = 1.f / l_i[1];
    const int r0 = qt * 128 + wid * 16 + (lane >> 2);
    const int cb = (lane & 3) * 2;
#pragma unroll
    for (int ot = 0; ot < 16; ot++) {
        const int d = ot * 8 + cb;
        size_t o0 = ((size_t)b * SEQ + r0) * HDIM + h * HD + d;
        size_t o1 = o0 + (size_t)8 * HDIM;
        float a0 = acc[ot][0] * inv0, a1 = acc[ot][1] * inv0;
        float a2 = acc[ot][2] * inv1, a3 = acc[ot][3] * inv1;
        uint32_t h0 = packbf(a0, a1);
        uint32_t l0 = packbf(a0 - bfx2_lo(h0), a1 - bfx2_hi(h0));
        uint32_t h1 = packbf(a2, a3);
        uint32_t l1 = packbf(a2 - bfx2_lo(h1), a3 - bfx2_hi(h1));
        *(uint32_t*)(Yh + o0) = h0;
        *(uint32_t*)(Yl + o0) = l0;
        *(uint32_t*)(Yh + o1) = h1;
        *(uint32_t*)(Yl + o1) = l1;
    }
}

// ---------------------------------------------------------------------------
extern "C" void kernel_launch(void* const* d_in, const int* in_sizes, int n_in,
                              void* d_out, int out_size)
{
    const float* x        = (const float*)d_in[0];
    const float* ve       = (const float*)d_in[1];
    const float* qkv_w    = (const float*)d_in[2];   // [3*HDIM, DIM]
    const float* lambdas  = (const float*)d_in[3];
    const float* c_proj_w = (const float*)d_in[4];   // [DIM, HDIM]
    float* out = (float*)d_out;

    float *qkv, *V;
    __nv_bfloat16 *Qh, *Ql, *Kh, *Kl, *Vh, *Vl;
    __nv_bfloat16 *Xh, *Xl, *Wqh, *Wql, *Wph, *Wpl, *Yh, *Yl;
    cudaGetSymbolAddress((void**)&qkv, g_qkv);
    cudaGetSymbolAddress((void**)&V, g_v);
    cudaGetSymbolAddress((void**)&Qh, g_qh);
    cudaGetSymbolAddress((void**)&Ql, g_ql);
    cudaGetSymbolAddress((void**)&Kh, g_kh);
    cudaGetSymbolAddress((void**)&Kl, g_kl);
    cudaGetSymbolAddress((void**)&Vh, g_vh);
    cudaGetSymbolAddress((void**)&Vl, g_vl);
    cudaGetSymbolAddress((void**)&Xh, g_xh);
    cudaGetSymbolAddress((void**)&Xl, g_xl);
    cudaGetSymbolAddress((void**)&Wqh, g_wqh);
    cudaGetSymbolAddress((void**)&Wql, g_wql);
    cudaGetSymbolAddress((void**)&Wph, g_wph);
    cudaGetSymbolAddress((void**)&Wpl, g_wpl);
    cudaGetSymbolAddress((void**)&Yh, g_yh);
    cudaGetSymbolAddress((void**)&Yl, g_yl);

    cudaFuncSetAttribute(gemm_bf16s, cudaFuncAttributeMaxDynamicSharedMemorySize, G_SMEM);
    cudaFuncSetAttribute(flash_mma, cudaFuncAttributeMaxDynamicSharedMemorySize, F_SMEM);

    // 0) pre-split operands to bf16 hi/lo
    {
        int n4 = BATCH * SEQ * DMODEL / 4;
        split_kernel<<<(n4 + 255) / 256, 256>>>(x, Xh, Xl, n4);
        n4 = 3 * HDIM * DMODEL / 4;
        split_kernel<<<(n4 + 255) / 256, 256>>>(qkv_w, Wqh, Wql, n4);
        n4 = DMODEL * HDIM / 4;
        split_kernel<<<(n4 + 255) / 256, 256>>>(c_proj_w, Wph, Wpl, n4);
    }

    // 1) qkv = x @ qkv_w^T
    gemm_bf16s<<<dim3(3 * HDIM / 128, BATCH * SEQ / 128), 256, G_SMEM>>>(
        Xh, Xl, Wqh, Wql, qkv, DMODEL, 3 * HDIM);

    // 2) rms-norm + rope + v-mix
    prep_kernel<<<BATCH * SEQ * NH, 128>>>(qkv, ve, lambdas, Qh, Ql, Kh, Kl, V);

    // 2b) V transpose + split
    vtrans_kernel<<<dim3(SEQ / 32, HD / 32, BATCH * NH), 256>>>(V, Vh, Vl);

    // 3) flash attention -> pre-split Yh/Yl
    flash_mma<<<dim3(SEQ / 128, BATCH * NH), 256, F_SMEM>>>(
        Qh, Ql, Kh, Kl, Vh, Vl, Yh, Yl);

    // 4) out = Y @ c_proj_w^T
    gemm_bf16s<<<dim3(DMODEL / 128, BATCH * SEQ / 128), 256, G_SMEM>>>(
        Yh, Yl, Wph, Wpl, out, HDIM, DMODEL);
}

// round 5
// speedup vs baseline: 1.0547x; 1.0547x over previous
#include <cuda_runtime.h>
#include <cuda_bf16.h>
#include <cstdint>
#include <math.h>

#define BATCH 4
#define SEQ   2048
#define DMODEL 1024
#define NH    8
#define HD    128
#define HDIM  1024

// ---------------------------------------------------------------------------
// Scratch (device globals: allocation-free rule)
// ---------------------------------------------------------------------------
__device__ float g_qkv[(size_t)BATCH * SEQ * 3 * HDIM];          // [B,T,3*HDIM]
__device__ float g_v[(size_t)BATCH * NH * SEQ * HD];             // [B,H,T,D] fp32
__device__ __nv_bfloat16 g_qh[(size_t)BATCH * NH * SEQ * HD];    // [B,H,T,D]
__device__ __nv_bfloat16 g_ql[(size_t)BATCH * NH * SEQ * HD];
__device__ __nv_bfloat16 g_kh[(size_t)BATCH * NH * SEQ * HD];
__device__ __nv_bfloat16 g_kl[(size_t)BATCH * NH * SEQ * HD];
__device__ __nv_bfloat16 g_vh[(size_t)BATCH * NH * HD * SEQ];    // [B,H,D,T]
__device__ __nv_bfloat16 g_vl[(size_t)BATCH * NH * HD * SEQ];
// pre-split GEMM operands
__device__ __nv_bfloat16 g_xh[(size_t)BATCH * SEQ * DMODEL];
__device__ __nv_bfloat16 g_xl[(size_t)BATCH * SEQ * DMODEL];
__device__ __nv_bfloat16 g_wqh[(size_t)3 * HDIM * DMODEL];
__device__ __nv_bfloat16 g_wql[(size_t)3 * HDIM * DMODEL];
__device__ __nv_bfloat16 g_wph[(size_t)DMODEL * HDIM];
__device__ __nv_bfloat16 g_wpl[(size_t)DMODEL * HDIM];
__device__ __nv_bfloat16 g_yh[(size_t)BATCH * SEQ * HDIM];       // flash out (split)
__device__ __nv_bfloat16 g_yl[(size_t)BATCH * SEQ * HDIM];

// ---------------------------------------------------------------------------
// PTX helpers
// ---------------------------------------------------------------------------
__device__ __forceinline__ uint32_t smem_u32(const void* p) {
    uint32_t a;
    asm("{ .reg .u64 t; cvta.to.shared.u64 t, %1; cvt.u32.u64 %0, t; }"
        : "=r"(a) : "l"(p));
    return a;
}

#define LDMX4(r, addr) \
    asm volatile("ldmatrix.sync.aligned.m8n8.x4.shared.b16 {%0,%1,%2,%3}, [%4];" \
        : "=r"((r)[0]), "=r"((r)[1]), "=r"((r)[2]), "=r"((r)[3]) : "r"(addr))

#define MMA_BF16(d, a, b0, b1) \
    asm volatile("mma.sync.aligned.m16n8k16.row.col.f32.bf16.bf16.f32 " \
        "{%0,%1,%2,%3},{%4,%5,%6,%7},{%8,%9},{%0,%1,%2,%3};" \
        : "+f"((d)[0]), "+f"((d)[1]), "+f"((d)[2]), "+f"((d)[3]) \
        : "r"((a)[0]), "r"((a)[1]), "r"((a)[2]), "r"((a)[3]), "r"(b0), "r"(b1))

#define CP_ASYNC16(dst, src) \
    asm volatile("cp.async.cg.shared.global [%0], [%1], 16;" :: "r"(dst), "l"(src) : "memory")
#define CP_COMMIT() asm volatile("cp.async.commit_group;" ::: "memory")
#define CP_WAIT0()  asm volatile("cp.async.wait_group 0;" ::: "memory")
#define CP_WAIT1()  asm volatile("cp.async.wait_group 1;" ::: "memory")

__device__ __forceinline__ uint32_t packbf(float e0, float e1) {
    uint32_t d;
    asm("cvt.rn.bf16x2.f32 %0, %1, %2;" : "=r"(d) : "f"(e1), "f"(e0));
    return d;
}
__device__ __forceinline__ float bfx2_lo(uint32_t p) { return __uint_as_float(p << 16); }
__device__ __forceinline__ float bfx2_hi(uint32_t p) { return __uint_as_float(p & 0xFFFF0000u); }

// ---------------------------------------------------------------------------
// split: fp32 -> bf16 hi/lo
// ---------------------------------------------------------------------------
__global__ __launch_bounds__(256) void split_kernel(
    const float* __restrict__ src, __nv_bfloat16* __restrict__ hi,
    __nv_bfloat16* __restrict__ lo, int n4)
{
    int i = blockIdx.x * 256 + threadIdx.x;
    if (i < n4) {
        float4 v = ((const float4*)src)[i];
        uint32_t h0 = packbf(v.x, v.y), h1 = packbf(v.z, v.w);
        uint32_t l0 = packbf(v.x - bfx2_lo(h0), v.y - bfx2_hi(h0));
        uint32_t l1 = packbf(v.z - bfx2_lo(h1), v.w - bfx2_hi(h1));
        ((uint2*)hi)[i] = make_uint2(h0, h1);
        ((uint2*)lo)[i] = make_uint2(l0, l1);
    }
}

// ===========================================================================
// bf16-split GEMM: C[M,N](fp32) = (Ah+Al)[M,K] @ (Bh+Bl)[N,K]^T, 3-term mma.
// CTA tile 256x128, 512 threads (16 warps as 4x4, warp tile 64x32),
// K-chunk 32, 3-stage cp.async pipeline.
// smem stage: Ah|Al (256 rows x 80B each) | Bh|Bl (128 rows x 80B each)
//   = 61440 B; 3 stages = 184320 B. 16 warps/SM -> 4 per SMSP.
// ===========================================================================
#define GA_PART  20480
#define GB_PART  10240
#define G_STAGE  (2 * GA_PART + 2 * GB_PART)      // 61440
#define G_SMEM   (3 * G_STAGE)                    // 184320

__global__ __launch_bounds__(512, 1) void gemm_bf16s(
    const __nv_bfloat16* __restrict__ Ah, const __nv_bfloat16* __restrict__ Al,
    const __nv_bfloat16* __restrict__ Bh, const __nv_bfloat16* __restrict__ Bl,
    float* __restrict__ C, int Kd, int Nd)
{
    extern __shared__ char smem[];
    const uint32_t sb = smem_u32(smem);
    const int tid = threadIdx.x;
    const int wid = tid >> 5, lane = tid & 31;
    const int wm = wid >> 2, wn = wid & 3;        // 4x4 warp grid
    const int m0 = blockIdx.y * 256, n0 = blockIdx.x * 128;
    const int nch = Kd / 32;

    auto load_stage = [&](int c) {
        const uint32_t st = sb + (c % 3) * G_STAGE;
        const __nv_bfloat16* pAh = Ah + (size_t)m0 * Kd + c * 32;
        const __nv_bfloat16* pAl = Al + (size_t)m0 * Kd + c * 32;
        const __nv_bfloat16* pBh = Bh + (size_t)n0 * Kd + c * 32;
        const __nv_bfloat16* pBl = Bl + (size_t)n0 * Kd + c * 32;
        // A: 256 rows x 4 16B-chunks per part
#pragma unroll
        for (int i = 0; i < 2; i++) {
            const int cc = i * 512 + tid;          // 0..1023
            const int row = cc >> 2, col = cc & 3;
            const uint32_t off = row * 80 + col * 16;
            const size_t gi = (size_t)row * Kd + col * 8;
            CP_ASYNC16(st + off,           pAh + gi);
            CP_ASYNC16(st + GA_PART + off, pAl + gi);
        }
        // B: 128 rows x 4 chunks per part
        {
            const int row = tid >> 2, col = tid & 3;
            const uint32_t off = row * 80 + col * 16;
            const size_t gi = (size_t)row * Kd + col * 8;
            CP_ASYNC16(st + 2 * GA_PART + off,           pBh + gi);
            CP_ASYNC16(st + 2 * GA_PART + GB_PART + off, pBl + gi);
        }
    };

    float acc[4][4][4];
#pragma unroll
    for (int i = 0; i < 4; i++)
#pragma unroll
        for (int j = 0; j < 4; j++)
#pragma unroll
            for (int e = 0; e < 4; e++) acc[i][j][e] = 0.f;

    auto compute = [&](int s) {
        const uint32_t st = sb + s * G_STAGE;
        const uint32_t lrow = (lane & 15);
        const uint32_t lcol = (lane >> 4) * 16;
#pragma unroll
        for (int k16 = 0; k16 < 2; k16++) {
            const uint32_t kb2 = k16 * 32;
            uint32_t ah[4][4], al[4][4];
#pragma unroll
            for (int i = 0; i < 4; i++) {
                uint32_t aaddr = st + (wm * 64 + i * 16 + lrow) * 80 + kb2 + lcol;
                LDMX4(ah[i], aaddr);
                LDMX4(al[i], aaddr + GA_PART);
            }
            uint32_t bh_[4][2], bl_[4][2];
#pragma unroll
            for (int jj = 0; jj < 2; jj++) {
                uint32_t r[4];
                uint32_t baddr = st + 2 * GA_PART + (wn * 32 + jj * 16 + lrow) * 80 + kb2 + lcol;
                LDMX4(r, baddr);
                bh_[2 * jj][0] = r[0]; bh_[2 * jj][1] = r[2];
                bh_[2 * jj + 1][0] = r[1]; bh_[2 * jj + 1][1] = r[3];
                LDMX4(r, baddr + GB_PART);
                bl_[2 * jj][0] = r[0]; bl_[2 * jj][1] = r[2];
                bl_[2 * jj + 1][0] = r[1]; bl_[2 * jj + 1][1] = r[3];
            }
#pragma unroll
            for (int i = 0; i < 4; i++)
#pragma unroll
                for (int j = 0; j < 4; j++) {
                    MMA_BF16(acc[i][j], ah[i], bh_[j][0], bh_[j][1]);
                    MMA_BF16(acc[i][j], al[i], bh_[j][0], bh_[j][1]);
                    MMA_BF16(acc[i][j], ah[i], bl_[j][0], bl_[j][1]);
                }
        }
    };

    load_stage(0); CP_COMMIT();
    if (nch > 1) { load_stage(1); CP_COMMIT(); }
    for (int c = 0; c < nch; c++) {
        if (c + 1 < nch) CP_WAIT1(); else CP_WAIT0();
        __syncthreads();
        if (c + 2 < nch) { load_stage(c + 2); CP_COMMIT(); }
        compute(c % 3);
    }

    // ---- epilogue ----
    const int r = lane >> 2;
    const int cb = (lane & 3) * 2;
#pragma unroll
    for (int i = 0; i < 4; i++) {
        const int row0 = m0 + wm * 64 + i * 16 + r;
#pragma unroll
        for (int j = 0; j < 4; j++) {
            const int col = n0 + wn * 32 + j * 8 + cb;
            *(float2*)(C + (size_t)row0 * Nd + col) = make_float2(acc[i][j][0], acc[i][j][1]);
            *(float2*)(C + (size_t)(row0 + 8) * Nd + col) = make_float2(acc[i][j][2], acc[i][j][3]);
        }
    }
}

// ---------------------------------------------------------------------------
// prep: per (b,t,h) RMS-norm q,k; RoPE; v-mix.
// ---------------------------------------------------------------------------
__global__ __launch_bounds__(128) void prep_kernel(
    const float* __restrict__ qkv, const float* __restrict__ ve,
    const float* __restrict__ lam,
    __nv_bfloat16* __restrict__ Qh, __nv_bfloat16* __restrict__ Ql,
    __nv_bfloat16* __restrict__ Kh, __nv_bfloat16* __restrict__ Kl,
    float* __restrict__ V)
{
    const int idx = blockIdx.x;
    const int h = idx % NH;
    const int bt = idx / NH;
    const int t = bt % SEQ;
    const int b = bt / SEQ;
    const int d = threadIdx.x;

    const float* base = qkv + (size_t)bt * 3 * HDIM;
    float qv = base[h * HD + d];
    float kv = base[HDIM + h * HD + d];
    float vv = base[2 * HDIM + h * HD + d];

    float sq = qv * qv, sk = kv * kv;
#pragma unroll
    for (int o = 16; o; o >>= 1) {
        sq += __shfl_xor_sync(0xffffffffu, sq, o);
        sk += __shfl_xor_sync(0xffffffffu, sk, o);
    }
    __shared__ float wq[4], wk[4];
    if ((d & 31) == 0) { wq[d >> 5] = sq; wk[d >> 5] = sk; }
    __syncthreads();
    float tq = (wq[0] + wq[1]) + (wq[2] + wq[3]);
    float tk = (wk[0] + wk[1]) + (wk[2] + wk[3]);
    const float EPS = 1.1920929e-7f;
    float rq = rsqrtf(tq * (1.0f / 128.0f) + EPS);
    float rk = rsqrtf(tk * (1.0f / 128.0f) + EPS);

    __shared__ float nq[128], nk[128];
    nq[d] = qv * rq;
    nk[d] = kv * rk;
    __syncthreads();

    const int i = d & 63;
    float c, s;
    if (i < 32) {
        float xi = (float)i / 31.0f;
        float f = (float)exp2(-10.0 * (double)xi);
        float th = (float)t * f;
        c = cosf(th);
        s = sinf(th);
    } else {
        c = 1.0f; s = 0.0f;
    }
    float qo, ko;
    if (d < 64) { qo = nq[d] * c + nq[d + 64] * s; ko = nk[d] * c + nk[d + 64] * s; }
    else        { qo = nq[d] * c - nq[d - 64] * s; ko = nk[d] * c - nk[d - 64] * s; }

    float vo = lam[0] * vv + lam[1] * ve[(size_t)bt * HDIM + h * HD + d];

    size_t o = ((size_t)(b * NH + h) * SEQ + t) * HD + d;
    __nv_bfloat16 qhi = __float2bfloat16(qo);
    __nv_bfloat16 khi = __float2bfloat16(ko);
    Qh[o] = qhi; Ql[o] = __float2bfloat16(qo - __bfloat162float(qhi));
    Kh[o] = khi; Kl[o] = __float2bfloat16(ko - __bfloat162float(khi));
    V[o] = vo;
}

// ---------------------------------------------------------------------------
// vtrans: V [BH][T][D] fp32 -> Vh/Vl [BH][D][T] bf16 split
// ---------------------------------------------------------------------------
__global__ __launch_bounds__(256) void vtrans_kernel(
    const float* __restrict__ V,
    __nv_bfloat16* __restrict__ Vh, __nv_bfloat16* __restrict__ Vl)
{
    __shared__ float tile[32][33];
    const int bh = blockIdx.z;
    const int t0 = blockIdx.x * 32, d0 = blockIdx.y * 32;
    const int tx = threadIdx.x & 31, ty = threadIdx.x >> 5;
    const float* src = V + (size_t)bh * SEQ * HD;
#pragma unroll
    for (int i = 0; i < 4; i++)
        tile[ty + i * 8][tx] = src[(size_t)(t0 + ty + i * 8) * HD + d0 + tx];
    __syncthreads();
    __nv_bfloat16* dh = Vh + (size_t)bh * HD * SEQ;
    __nv_bfloat16* dl = Vl + (size_t)bh * HD * SEQ;
#pragma unroll
    for (int i = 0; i < 4; i++) {
        float v = tile[tx][ty + i * 8];
        __nv_bfloat16 hi = __float2bfloat16(v);
        size_t o = (size_t)(d0 + ty + i * 8) * SEQ + t0 + tx;
        dh[o] = hi;
        dl[o] = __float2bfloat16(v - __bfloat162float(hi));
    }
}

// ===========================================================================
// Flash attention, bf16-split mma. 128 q-rows/CTA, 8 warps x 16 rows.
// ===========================================================================
#define FQ_PART 34816
#define FK_PART 17408
#define FV_PART 18432
#define FSTAGE  (2 * FK_PART + 2 * FV_PART)
#define FSTAGE0 (2 * FQ_PART)
#define F_SMEM  (FSTAGE0 + 2 * FSTAGE)

__global__ __launch_bounds__(256, 1) void flash_mma(
    const __nv_bfloat16* __restrict__ Qh, const __nv_bfloat16* __restrict__ Ql,
    const __nv_bfloat16* __restrict__ Kh, const __nv_bfloat16* __restrict__ Kl,
    const __nv_bfloat16* __restrict__ Vh, const __nv_bfloat16* __restrict__ Vl,
    __nv_bfloat16* __restrict__ Yh, __nv_bfloat16* __restrict__ Yl)
{
    extern __shared__ char smem[];
    const uint32_t sbase = smem_u32(smem);
    const int tid = threadIdx.x;
    const int wid = tid >> 5, lane = tid & 31;
    const int qt = gridDim.x - 1 - blockIdx.x;
    const int bh = blockIdx.y;
    const int b = bh >> 3, h = bh & 7;

    const size_t TD = (size_t)SEQ * HD;
    const __nv_bfloat16* qh_b = Qh + bh * TD;
    const __nv_bfloat16* ql_b = Ql + bh * TD;
    const __nv_bfloat16* kh_b = Kh + bh * TD;
    const __nv_bfloat16* kl_b = Kl + bh * TD;
    const __nv_bfloat16* vh_b = Vh + bh * TD;
    const __nv_bfloat16* vl_b = Vl + bh * TD;

#pragma unroll
    for (int i = 0; i < 16; i++) {
        int c = i * 256 + tid;
        int part = c >> 11;
        int c2 = c & 2047;
        int row = c2 >> 4, col = c2 & 15;
        uint32_t dst = sbase + part * FQ_PART + row * 272 + col * 16;
        const __nv_bfloat16* src = (part ? ql_b : qh_b) + (size_t)(qt * 128 + row) * 128 + col * 8;
        CP_ASYNC16(dst, src);
    }
    auto load_kv = [&](int kt, int s) {
        uint32_t kb = sbase + FSTAGE0 + s * FSTAGE;
#pragma unroll
        for (int i = 0; i < 4; i++) {
            int c = i * 256 + tid;
            int row = c >> 4, col = c & 15;
            uint32_t off = row * 272 + col * 16;
            size_t gi = (size_t)(kt * 64 + row) * 128 + col * 8;
            CP_ASYNC16(kb + off, kh_b + gi);
            CP_ASYNC16(kb + FK_PART + off, kl_b + gi);
        }
#pragma unroll
        for (int i = 0; i < 4; i++) {
            int c = i * 256 + tid;
            int row = c >> 3, col = c & 7;
            uint32_t off = row * 144 + col * 16;
            size_t gi = (size_t)row * SEQ + kt * 64 + col * 8;
            CP_ASYNC16(kb + 2 * FK_PART + off, vh_b + gi);
            CP_ASYNC16(kb + 2 * FK_PART + FV_PART + off, vl_b + gi);
        }
    };
    load_kv(0, 0);
    CP_COMMIT();

    float acc[16][4];
#pragma unroll
    for (int i = 0; i < 16; i++)
#pragma unroll
        for (int e = 0; e < 4; e++) acc[i][e] = 0.f;
    float m_i[2] = {-1e30f, -1e30f};
    float l_i[2] = {0.f, 0.f};

    const uint32_t lrow = lane & 15;
    const uint32_t lcol = (lane >> 4) * 16;
    const int nkt = 2 * qt + 2;
    const float SC = 0.08838834764831845f;

    for (int kt = 0; kt < nkt; kt++) {
        if (kt + 1 < nkt) {
            load_kv(kt + 1, (kt + 1) & 1);
            CP_COMMIT();
            CP_WAIT1();
        } else {
            CP_WAIT0();
        }
        __syncthreads();
        const uint32_t kb = sbase + FSTAGE0 + (kt & 1) * FSTAGE;

        float s[8][4];
#pragma unroll
        for (int j = 0; j < 8; j++)
#pragma unroll
            for (int e = 0; e < 4; e++) s[j][e] = 0.f;

        const uint32_t qrow = sbase + (wid * 16 + lrow) * 272 + lcol;
#pragma unroll
        for (int k16 = 0; k16 < 8; k16++) {
            uint32_t qa = qrow + k16 * 32;
            uint32_t ah[4], al[4];
            LDMX4(ah, qa);
            LDMX4(al, qa + FQ_PART);
#pragma unroll
            for (int jj = 0; jj < 4; jj++) {
                uint32_t ka = kb + (jj * 16 + lrow) * 272 + lcol + k16 * 32;
                uint32_t r[4];
                LDMX4(r, ka);
                MMA_BF16(s[2 * jj], ah, r[0], r[2]);
                MMA_BF16(s[2 * jj + 1], ah, r[1], r[3]);
                MMA_BF16(s[2 * jj], al, r[0], r[2]);
                MMA_BF16(s[2 * jj + 1], al, r[1], r[3]);
                LDMX4(r, ka + FK_PART);
                MMA_BF16(s[2 * jj], ah, r[0], r[2]);
                MMA_BF16(s[2 * jj + 1], ah, r[1], r[3]);
            }
        }

        const bool need_mask = (kt >= 2 * qt);
#pragma unroll
        for (int hh = 0; hh < 2; hh++) {
            const int rowg = qt * 128 + wid * 16 + (lane >> 2) + hh * 8;
            float mt = -1e30f;
#pragma unroll
            for (int j = 0; j < 8; j++) {
#pragma unroll
                for (int e = 0; e < 2; e++) {
                    float v = s[j][2 * hh + e] * SC;
                    if (need_mask) {
                        int colg = kt * 64 + j * 8 + (lane & 3) * 2 + e;
                        if (colg > rowg) v = -1e30f;
                    }
                    s[j][2 * hh + e] = v;
                    mt = fmaxf(mt, v);
                }
            }
            mt = fmaxf(mt, __shfl_xor_sync(0xffffffffu, mt, 1));
            mt = fmaxf(mt, __shfl_xor_sync(0xffffffffu, mt, 2));
            float mn = fmaxf(m_i[hh], mt);
            float corr = __expf(m_i[hh] - mn);
            m_i[hh] = mn;
            float rs = 0.f;
#pragma unroll
            for (int j = 0; j < 8; j++) {
#pragma unroll
                for (int e = 0; e < 2; e++) {
                    float p = __expf(s[j][2 * hh + e] - mn);
                    s[j][2 * hh + e] = p;
                    rs += p;
                }
            }
            rs += __shfl_xor_sync(0xffffffffu, rs, 1);
            rs += __shfl_xor_sync(0xffffffffu, rs, 2);
            l_i[hh] = l_i[hh] * corr + rs;
#pragma unroll
            for (int ot = 0; ot < 16; ot++) {
                acc[ot][2 * hh] *= corr;
                acc[ot][2 * hh + 1] *= corr;
            }
        }

        const uint32_t vb = kb + 2 * FK_PART;
#pragma unroll
        for (int kk = 0; kk < 4; kk++) {
            const int j0 = 2 * kk, j1 = 2 * kk + 1;
            uint32_t ahp[4], alp[4];
            ahp[0] = packbf(s[j0][0], s[j0][1]);
            ahp[1] = packbf(s[j0][2], s[j0][3]);
            ahp[2] = packbf(s[j1][0], s[j1][1]);
            ahp[3] = packbf(s[j1][2], s[j1][3]);
            alp[0] = packbf(s[j0][0] - bfx2_lo(ahp[0]), s[j0][1] - bfx2_hi(ahp[0]));
            alp[1] = packbf(s[j0][2] - bfx2_lo(ahp[1]), s[j0][3] - bfx2_hi(ahp[1]));
            alp[2] = packbf(s[j1][0] - bfx2_lo(ahp[2]), s[j1][1] - bfx2_hi(ahp[2]));
            alp[3] = packbf(s[j1][2] - bfx2_lo(ahp[3]), s[j1][3] - bfx2_hi(ahp[3]));
#pragma unroll
            for (int jj = 0; jj < 8; jj++) {
                uint32_t va = vb + (jj * 16 + lrow) * 144 + kk * 32 + lcol;
                uint32_t r[4];
                LDMX4(r, va);
                MMA_BF16(acc[2 * jj], ahp, r[0], r[2]);
                MMA_BF16(acc[2 * jj + 1], ahp, r[1], r[3]);
                MMA_BF16(acc[2 * jj], alp, r[0], r[2]);
                MMA_BF16(acc[2 * jj + 1], alp, r[1], r[3]);
                LDMX4(r, va + FV_PART);
                MMA_BF16(acc[2 * jj], ahp, r[0], r[2]);
                MMA_BF16(acc[2 * jj + 1], ahp, r[1], r[3]);
            }
        }
        __syncthreads();
    }

    // ---------- epilogue: write pre-split bf16 Y ----------
    const float inv0 = 1.f / l_i[0];
    const float inv1 = 1.f / l_i[1];
    const int r0 = qt * 128 + wid * 16 + (lane >> 2);
    const int cb = (lane & 3) * 2;
#pragma unroll
    for (int ot = 0; ot < 16; ot++) {
        const int d = ot * 8 + cb;
        size_t o0 = ((size_t)b * SEQ + r0) * HDIM + h * HD + d;
        size_t o1 = o0 + (size_t)8 * HDIM;
        float a0 = acc[ot][0] * inv0, a1 = acc[ot][1] * inv0;
        float a2 = acc[ot][2] * inv1, a3 = acc[ot][3] * inv1;
        uint32_t h0 = packbf(a0, a1);
        uint32_t l0 = packbf(a0 - bfx2_lo(h0), a1 - bfx2_hi(h0));
        uint32_t h1 = packbf(a2, a3);
        uint32_t l1 = packbf(a2 - bfx2_lo(h1), a3 - bfx2_hi(h1));
        *(uint32_t*)(Yh + o0) = h0;
        *(uint32_t*)(Yl + o0) = l0;
        *(uint32_t*)(Yh + o1) = h1;
        *(uint32_t*)(Yl + o1) = l1;
    }
}

// ---------------------------------------------------------------------------
extern "C" void kernel_launch(void* const* d_in, const int* in_sizes, int n_in,
                              void* d_out, int out_size)
{
    const float* x        = (const float*)d_in[0];
    const float* ve       = (const float*)d_in[1];
    const float* qkv_w    = (const float*)d_in[2];   // [3*HDIM, DIM]
    const float* lambdas  = (const float*)d_in[3];
    const float* c_proj_w = (const float*)d_in[4];   // [DIM, HDIM]
    float* out = (float*)d_out;

    float *qkv, *V;
    __nv_bfloat16 *Qh, *Ql, *Kh, *Kl, *Vh, *Vl;
    __nv_bfloat16 *Xh, *Xl, *Wqh, *Wql, *Wph, *Wpl, *Yh, *Yl;
    cudaGetSymbolAddress((void**)&qkv, g_qkv);
    cudaGetSymbolAddress((void**)&V, g_v);
    cudaGetSymbolAddress((void**)&Qh, g_qh);
    cudaGetSymbolAddress((void**)&Ql, g_ql);
    cudaGetSymbolAddress((void**)&Kh, g_kh);
    cudaGetSymbolAddress((void**)&Kl, g_kl);
    cudaGetSymbolAddress((void**)&Vh, g_vh);
    cudaGetSymbolAddress((void**)&Vl, g_vl);
    cudaGetSymbolAddress((void**)&Xh, g_xh);
    cudaGetSymbolAddress((void**)&Xl, g_xl);
    cudaGetSymbolAddress((void**)&Wqh, g_wqh);
    cudaGetSymbolAddress((void**)&Wql, g_wql);
    cudaGetSymbolAddress((void**)&Wph, g_wph);
    cudaGetSymbolAddress((void**)&Wpl, g_wpl);
    cudaGetSymbolAddress((void**)&Yh, g_yh);
    cudaGetSymbolAddress((void**)&Yl, g_yl);

    cudaFuncSetAttribute(gemm_bf16s, cudaFuncAttributeMaxDynamicSharedMemorySize, G_SMEM);
    cudaFuncSetAttribute(flash_mma, cudaFuncAttributeMaxDynamicSharedMemorySize, F_SMEM);

    // 0) pre-split operands to bf16 hi/lo
    {
        int n4 = BATCH * SEQ * DMODEL / 4;
        split_kernel<<<(n4 + 255) / 256, 256>>>(x, Xh, Xl, n4);
        n4 = 3 * HDIM * DMODEL / 4;
        split_kernel<<<(n4 + 255) / 256, 256>>>(qkv_w, Wqh, Wql, n4);
        n4 = DMODEL * HDIM / 4;
        split_kernel<<<(n4 + 255) / 256, 256>>>(c_proj_w, Wph, Wpl, n4);
    }

    // 1) qkv = x @ qkv_w^T
    gemm_bf16s<<<dim3(3 * HDIM / 128, BATCH * SEQ / 256), 512, G_SMEM>>>(
        Xh, Xl, Wqh, Wql, qkv, DMODEL, 3 * HDIM);

    // 2) rms-norm + rope + v-mix
    prep_kernel<<<BATCH * SEQ * NH, 128>>>(qkv, ve, lambdas, Qh, Ql, Kh, Kl, V);

    // 2b) V transpose + split
    vtrans_kernel<<<dim3(SEQ / 32, HD / 32, BATCH * NH), 256>>>(V, Vh, Vl);

    // 3) flash attention -> pre-split Yh/Yl
    flash_mma<<<dim3(SEQ / 128, BATCH * NH), 256, F_SMEM>>>(
        Qh, Ql, Kh, Kl, Vh, Vl, Yh, Yl);

    // 4) out = Y @ c_proj_w^T
    gemm_bf16s<<<dim3(DMODEL / 128, BATCH * SEQ / 256), 512, G_SMEM>>>(
        Yh, Yl, Wph, Wpl, out, HDIM, DMODEL);
}